// round 1
// baseline (speedup 1.0000x reference)
#include <cuda_runtime.h>

// dims
constexpr int Bn = 16, Nn = 2000, En = 3000, Cn = 17, Wn_ = 12, Dn = 16, On = 256, Kk = 3, NBn = 3;
constexpr int BC = Bn * Cn;   // 272
constexpr int KC = Kk * Cn;   // 51
constexpr int O4 = On / 4, O8 = On / 8, O2 = On / 2;
constexpr int R48 = Bn * NBn; // 48

#define NEG_HUGE -1e30f

// ---------------- scratch (static device globals; no allocs) ----------------
__device__ float g_neT[Dn * Nn];
__device__ float g_S[(size_t)Nn * Nn];          // 16 MB
__device__ float g_r[Nn];
__device__ float g_W[(size_t)Nn * KC * O4];     // 26 MB adaptive weights
__device__ float g_wwt[Nn * O2];
__device__ float g_wws[Nn * O8];
__device__ float g_bias[Nn * On];
__device__ float g_X0[Nn * BC];
__device__ float g_Y1[Nn * BC];
__device__ float g_Y1s[Nn * BC];
__device__ float g_Y2[Nn * BC];
__device__ float g_XE[R48 * En];
__device__ float g_hpart[3 * R48 * En];
__device__ float g_XEST[En * R48];
__device__ float g_ipart[2 * Nn * R48];
__device__ float g_Mm[Bn * Nn];
__device__ float g_G[Nn];
__device__ float g_ts[Bn * Nn];

// ---------------- helpers ----------------
__device__ __forceinline__ float blk_reduce(float v, float* red, bool do_max) {
    int tid = threadIdx.x;
    red[tid] = v;
    __syncthreads();
#pragma unroll
    for (int s = 128; s > 0; s >>= 1) {
        if (tid < s) red[tid] = do_max ? fmaxf(red[tid], red[tid + s]) : (red[tid] + red[tid + s]);
        __syncthreads();
    }
    float r = red[0];
    __syncthreads();
    return r;
}

// ---------------- kernels ----------------

__global__ void k_transpose_ne(const float* __restrict__ ne) {
    int idx = blockIdx.x * 256 + threadIdx.x;
    if (idx < Nn * Dn) {
        int n = idx >> 4, d = idx & 15;
        g_neT[d * Nn + n] = ne[idx];
    }
}

// C(M,Nc) = A(M,16) @ B(16,Nc). EPI=1: relu then diag=stay_cost (for S0)
template <int EPI>
__global__ void k_gemm_k16(const float* __restrict__ A, const float* __restrict__ B,
                           float* __restrict__ C, int M, int Nc, const int* __restrict__ stay_ptr) {
    __shared__ float As[32][17];
    __shared__ float Bs[16][64];
    int tid = threadIdx.x;
    int m0 = blockIdx.y * 32, n0 = blockIdx.x * 64;
    for (int i = tid; i < 512; i += 256) {
        int mm = i >> 4, kk = i & 15;
        int gm = m0 + mm;
        As[mm][kk] = (gm < M) ? A[gm * 16 + kk] : 0.f;
    }
    for (int i = tid; i < 1024; i += 256) {
        int kk = i >> 6, nn = i & 63;
        int gn = n0 + nn;
        Bs[kk][nn] = (gn < Nc) ? B[kk * Nc + gn] : 0.f;
    }
    __syncthreads();
    int tx = tid & 63, ty = tid >> 6;
    float acc[8] = {0, 0, 0, 0, 0, 0, 0, 0};
#pragma unroll
    for (int d = 0; d < 16; d++) {
        float bv = Bs[d][tx];
#pragma unroll
        for (int i = 0; i < 8; i++) acc[i] += As[ty * 8 + i][d] * bv;
    }
    int gn = n0 + tx;
    if (gn < Nc) {
#pragma unroll
        for (int i = 0; i < 8; i++) {
            int gm = m0 + ty * 8 + i;
            if (gm < M) {
                float v = acc[i];
                if (EPI == 1) {
                    v = fmaxf(v, 0.f);
                    if (gm == gn) v = (float)stay_ptr[0];
                }
                C[(size_t)gm * Nc + gn] = v;
            }
        }
    }
}

// per-row: softmax (fixed_adj==0) or adj*exp (else); writes row back + rowsum r
__global__ void k_row_transform(const float* __restrict__ adj, const int* __restrict__ fa_ptr) {
    __shared__ float red[256];
    int row = blockIdx.x, tid = threadIdx.x;
    float* srow = g_S + (size_t)row * Nn;
    float v[8];
#pragma unroll
    for (int i = 0; i < 8; i++) {
        int idx = i * 256 + tid;
        v[i] = (idx < Nn) ? srow[idx] : NEG_HUGE;
    }
    float rsum;
    if (fa_ptr[0] == 0) {
        float m = NEG_HUGE;
#pragma unroll
        for (int i = 0; i < 8; i++) m = fmaxf(m, v[i]);
        m = blk_reduce(m, red, true);
        float z = 0.f;
#pragma unroll
        for (int i = 0; i < 8; i++) {
            v[i] = expf(v[i] - m);  // oob lanes: exp(-huge) = 0
            z += v[i];
        }
        z = blk_reduce(z, red, false);
        float inv = 1.f / z;
        float s2 = 0.f;
#pragma unroll
        for (int i = 0; i < 8; i++) {
            v[i] *= inv;
            s2 += v[i];
        }
        rsum = blk_reduce(s2, red, false);
    } else {
        float s2 = 0.f;
#pragma unroll
        for (int i = 0; i < 8; i++) {
            int idx = i * 256 + tid;
            float sv = 0.f;
            if (idx < Nn) sv = adj[(size_t)row * Nn + idx] * expf(v[i]);
            v[i] = sv;
            s2 += sv;
        }
        rsum = blk_reduce(s2, red, false);
    }
#pragma unroll
    for (int i = 0; i < 8; i++) {
        int idx = i * 256 + tid;
        if (idx < Nn) srow[idx] = v[i];
    }
    if (tid == 0) g_r[row] = rsum;
}

__global__ void k_prep_x0(const float* __restrict__ x) {
    int idx = blockIdx.x * 256 + threadIdx.x;
    if (idx < Nn * BC) {
        int n = idx / BC, j = idx % BC;
        int b = j / Cn, c = j % Cn;
        g_X0[idx] = x[((size_t)b * Nn + n) * Cn + c] / g_r[n];
    }
}

__global__ void k_scale_y1() {
    int idx = blockIdx.x * 256 + threadIdx.x;
    if (idx < Nn * BC) {
        int n = idx / BC;
        g_Y1s[idx] = g_Y1[idx] / g_r[n];
    }
}

__global__ void k_prep_xe(const float* __restrict__ xew, const int* __restrict__ bidx,
                          const float* __restrict__ lw, const float* __restrict__ lb) {
    int idx = blockIdx.x * 256 + threadIdx.x;
    if (idx < R48 * En) {
        int r = idx / En, e = idx % En;
        int b = r / NBn, f = r % NBn;
        int t = bidx[f];
        g_XE[idx] = xew[((size_t)(b * Wn_ + t)) * En + e] * lw[0] + lb[0];
    }
}

__global__ void k_tsum(const float* __restrict__ xw, const float* __restrict__ Tp) {
    int idx = blockIdx.x * 256 + threadIdx.x;
    if (idx < Bn * Nn) {
        int b = idx / Nn, n = idx % Nn;
        float s = 0.f;
#pragma unroll
        for (int t = 0; t < Wn_; t++) s += xw[((size_t)(b * Wn_ + t)) * Nn + n] * Tp[t];
        g_ts[idx] = s;
    }
}

__global__ void k_rowsum_g(const float* __restrict__ gw) {
    __shared__ float red[256];
    int row = blockIdx.x, tid = threadIdx.x;
    float s = 0.f;
    for (int i = tid; i < Nn; i += 256) s += gw[(size_t)row * Nn + i];
    s = blk_reduce(s, red, false);
    if (tid == 0) g_G[row] = s;
}

// reduce split-K hodge partials + jump-cost prefix, write transposed (E,48)
__global__ void k_hreduce(const int* __restrict__ jump_ptr) {
    int e = blockIdx.x * 256 + threadIdx.x;
    int r = blockIdx.y;
    if (e < En) {
        float v = g_hpart[r * En + e] + g_hpart[R48 * En + r * En + e] + g_hpart[2 * R48 * En + r * En + e];
        int b = r / NBn, f = r % NBn;
        float jc = (float)jump_ptr[0];
        for (int fp = 0; fp < f; fp++) v += jc * g_XE[(b * NBn + fp) * En + e];
        g_XEST[e * R48 + r] = v;
    }
}

// reduce split-K incidence partials + mean over bootstrap frames
__global__ void k_mreduce() {
    int idx = blockIdx.x * 256 + threadIdx.x;
    if (idx < Bn * Nn) {
        int b = idx / Nn, n = idx % Nn;
        float v = 0.f;
#pragma unroll
        for (int f = 0; f < NBn; f++) {
            int r = b * NBn + f;
            v += g_ipart[n * R48 + r] + g_ipart[(size_t)Nn * R48 + n * R48 + r];
        }
        g_Mm[idx] = v * (1.f / NBn);
    }
}

// generic tiled fp32 SGEMM with optional split-K over blockIdx.z (partial planes)
template <int BM, int BN, int BK, int TM, int TN>
__global__ void k_sgemm(const float* __restrict__ A, const float* __restrict__ B,
                        float* __restrict__ C, int M, int N, int K) {
    constexpr int TXc = BN / TN, TYc = BM / TM, NT = TXc * TYc;
    __shared__ float As[BM][BK + 1];
    __shared__ float Bs[BK][BN + 1];
    int tid = threadIdx.x;
    int tx = tid % TXc, ty = tid / TXc;
    int m0 = blockIdx.y * BM, n0 = blockIdx.x * BN;
    int kChunk = (K + gridDim.z - 1) / gridDim.z;
    int k0 = blockIdx.z * kChunk;
    int k1 = min(K, k0 + kChunk);
    float acc[TM][TN];
#pragma unroll
    for (int i = 0; i < TM; i++)
#pragma unroll
        for (int j = 0; j < TN; j++) acc[i][j] = 0.f;
    for (int kb = k0; kb < k1; kb += BK) {
        for (int i = tid; i < BM * BK; i += NT) {
            int mm = i / BK, kk = i % BK;
            int gm = m0 + mm, gk = kb + kk;
            As[mm][kk] = (gm < M && gk < k1) ? A[(size_t)gm * K + gk] : 0.f;
        }
        for (int i = tid; i < BK * BN; i += NT) {
            int kk = i / BN, nn = i % BN;
            int gk = kb + kk, gn = n0 + nn;
            Bs[kk][nn] = (gk < k1 && gn < N) ? B[(size_t)gk * N + gn] : 0.f;
        }
        __syncthreads();
#pragma unroll
        for (int kk = 0; kk < BK; kk++) {
            float ra[TM], rb[TN];
#pragma unroll
            for (int i = 0; i < TM; i++) ra[i] = As[ty * TM + i][kk];
#pragma unroll
            for (int j = 0; j < TN; j++) rb[j] = Bs[kk][tx * TN + j];
#pragma unroll
            for (int i = 0; i < TM; i++)
#pragma unroll
                for (int j = 0; j < TN; j++) acc[i][j] += ra[i] * rb[j];
        }
        __syncthreads();
    }
    float* Cp = C + (size_t)blockIdx.z * M * N;
#pragma unroll
    for (int i = 0; i < TM; i++) {
        int gm = m0 + ty * TM + i;
        if (gm < M) {
#pragma unroll
            for (int j = 0; j < TN; j++) {
                int gn = n0 + tx * TN + j;
                if (gn < N) Cp[(size_t)gm * N + gn] = acc[i][j];
            }
        }
    }
}

// fused per-node epilogue: diffusion conv + ZFC + temporal + supra + bias
__global__ void k_epilogue(const float* __restrict__ x, const float* __restrict__ zin,
                           const float* __restrict__ gnnb, float* __restrict__ out) {
    __shared__ float Wns[KC * O4];   // 3264
    __shared__ float xs[Bn * 52];
    __shared__ float bias_s[On];
    __shared__ float wwt_s[O2];
    __shared__ float wws_s[O8];
    __shared__ float ts_s[Bn];
    __shared__ float Ms_s[Bn];
    int n = blockIdx.x, tid = threadIdx.x;
    for (int i = tid; i < KC * O4; i += 256) Wns[i] = g_W[(size_t)n * KC * O4 + i];
    for (int i = tid; i < Bn * KC; i += 256) {
        int b = i / KC, kc = i % KC;
        int k = kc / Cn, c = kc % Cn;
        float v;
        if (k == 0) v = x[((size_t)b * Nn + n) * Cn + c];
        else if (k == 1) v = g_Y1[n * BC + b * Cn + c];
        else v = g_Y2[n * BC + b * Cn + c];
        xs[b * 52 + kc] = v;
    }
    bias_s[tid] = g_bias[n * On + tid];
    if (tid < O2) wwt_s[tid] = g_wwt[n * O2 + tid];
    if (tid < O8) wws_s[tid] = g_wws[n * O8 + tid];
    if (tid < Bn) {
        ts_s[tid] = g_ts[tid * Nn + n];
        Ms_s[tid] = g_Mm[tid * Nn + n];
    }
    __syncthreads();
    int b = tid >> 4;
    int oc = (tid & 15) * 4;
    float acc[4] = {0, 0, 0, 0};
    for (int kc = 0; kc < KC; kc++) {
        float a = xs[b * 52 + kc];
#pragma unroll
        for (int j = 0; j < 4; j++) acc[j] += a * Wns[kc * O4 + oc + j];
    }
    float* orow = out + ((size_t)b * Nn + n) * On;
#pragma unroll
    for (int j = 0; j < 4; j++) orow[oc + j] = acc[j] + bias_s[oc + j];
#pragma unroll
    for (int it = 0; it < 12; it++) {
        int o = 64 + (tid & 15) + it * 16;
        float v;
        if (o < 96) {
            int c = o - 64;
            int flat = n * O8 + c;
            int i2 = flat / Nn;
            int m = flat - i2 * Nn;
            v = fmaxf(zin[b * O8 + i2] * g_G[m] + gnnb[m], 0.f);
        } else if (o < 224) {
            v = ts_s[b] * wwt_s[o - 96];
        } else {
            v = Ms_s[b] * wws_s[o - 224];
        }
        orow[o] = v + bias_s[o];
    }
}

// ---------------- launch ----------------
extern "C" void kernel_launch(void* const* d_in, const int* in_sizes, int n_in,
                              void* d_out, int out_size) {
    const float* x    = (const float*)d_in[0];
    const float* xw   = (const float*)d_in[1];
    const float* ne   = (const float*)d_in[2];
    const int*   fa   = (const int*)d_in[3];
    const float* adj  = (const float*)d_in[4];
    const int*   stay = (const int*)d_in[5];
    const int*   jump = (const int*)d_in[6];
    const float* zin  = (const float*)d_in[7];
    const float* hodge= (const float*)d_in[8];
    const float* xew  = (const float*)d_in[9];
    const float* inc  = (const float*)d_in[10];
    const float* wp   = (const float*)d_in[11];
    const float* wwsp = (const float*)d_in[12];
    const float* wwtp = (const float*)d_in[13];
    const float* bp   = (const float*)d_in[14];
    const float* Tp   = (const float*)d_in[15];
    const float* lw   = (const float*)d_in[16];
    const float* lb   = (const float*)d_in[17];
    const float* gw   = (const float*)d_in[18];
    const float* gb   = (const float*)d_in[19];
    const int*   bidx = (const int*)d_in[20];
    float* out = (float*)d_out;

    float *pNeT, *pS, *pW, *pWwt, *pWws, *pBias, *pX0, *pY1, *pY1s, *pY2, *pXE, *pH, *pXEST, *pI;
    cudaGetSymbolAddress((void**)&pNeT, g_neT);
    cudaGetSymbolAddress((void**)&pS, g_S);
    cudaGetSymbolAddress((void**)&pW, g_W);
    cudaGetSymbolAddress((void**)&pWwt, g_wwt);
    cudaGetSymbolAddress((void**)&pWws, g_wws);
    cudaGetSymbolAddress((void**)&pBias, g_bias);
    cudaGetSymbolAddress((void**)&pX0, g_X0);
    cudaGetSymbolAddress((void**)&pY1, g_Y1);
    cudaGetSymbolAddress((void**)&pY1s, g_Y1s);
    cudaGetSymbolAddress((void**)&pY2, g_Y2);
    cudaGetSymbolAddress((void**)&pXE, g_XE);
    cudaGetSymbolAddress((void**)&pH, g_hpart);
    cudaGetSymbolAddress((void**)&pXEST, g_XEST);
    cudaGetSymbolAddress((void**)&pI, g_ipart);

    // S branch
    k_transpose_ne<<<(Nn * Dn + 255) / 256, 256>>>(ne);
    k_gemm_k16<1><<<dim3(32, 63), 256>>>(ne, pNeT, pS, Nn, Nn, stay);       // S0 = relu(ne@neT), diag=stay
    k_row_transform<<<Nn, 256>>>(adj, fa);                                  // softmax (or adj*exp) + rowsums

    // adaptive params (independent)
    k_gemm_k16<0><<<dim3(51, 63), 256>>>(ne, wp, pW, Nn, KC * O4, nullptr); // weights
    k_gemm_k16<0><<<dim3(2, 63), 256>>>(ne, wwtp, pWwt, Nn, O2, nullptr);
    k_gemm_k16<0><<<dim3(1, 63), 256>>>(ne, wwsp, pWws, Nn, O8, nullptr);
    k_gemm_k16<0><<<dim3(4, 63), 256>>>(ne, bp, pBias, Nn, On, nullptr);

    // diffusion: Y1 = S @ (x/r), Y2 = S @ (Y1/r)
    k_prep_x0<<<(Nn * BC + 255) / 256, 256>>>(x);
    k_sgemm<128, 32, 16, 8, 2><<<dim3(9, 16, 1), 256>>>(pS, pX0, pY1, Nn, BC, Nn);
    k_scale_y1<<<(Nn * BC + 255) / 256, 256>>>();
    k_sgemm<128, 32, 16, 8, 2><<<dim3(9, 16, 1), 256>>>(pS, pY1s, pY2, Nn, BC, Nn);

    // supra branch (structured supra-Laplacian, never materialized)
    k_prep_xe<<<(R48 * En + 255) / 256, 256>>>(xew, bidx, lw, lb);
    k_sgemm<48, 64, 32, 3, 4><<<dim3(47, 1, 3), 256>>>(pXE, hodge, pH, R48, En, En);
    k_hreduce<<<dim3((En + 255) / 256, R48), 256>>>(jump);
    k_sgemm<32, 48, 32, 2, 3><<<dim3(1, 63, 2), 256>>>(inc, pXEST, pI, Nn, R48, En);
    k_mreduce<<<(Bn * Nn + 255) / 256, 256>>>();

    // temporal + ZFC precompute
    k_tsum<<<(Bn * Nn + 255) / 256, 256>>>(xw, Tp);
    k_rowsum_g<<<Nn, 256>>>(gw);

    // fused epilogue: assemble all four regions + bias
    k_epilogue<<<Nn, 256>>>(x, zin, gb, out);
}

// round 3
// speedup vs baseline: 1.6128x; 1.6128x over previous
#include <cuda_runtime.h>

typedef unsigned long long ull;

// dims
constexpr int Bn = 16, Nn = 2000, En = 3000, Cn = 17, Wn_ = 12, Dn = 16, On = 256, Kk = 3, NBn = 3;
constexpr int BC = Bn * Cn;   // 272
constexpr int BCp = 288;      // padded column count for diffusion GEMMs
constexpr int KC = Kk * Cn;   // 51
constexpr int O4 = On / 4, O8 = On / 8, O2 = On / 2;
constexpr int R48 = Bn * NBn; // 48
constexpr int SPL = 6;        // split-K planes

#define NEG_HUGE -1e30f

// ---------------- scratch (static device globals; no allocs) ----------------
__device__ float g_neT[Dn * Nn];
__device__ float g_S[(size_t)Nn * Nn];          // 16 MB
__device__ float g_r[Nn];
__device__ float g_W[(size_t)Nn * KC * O4];     // 26 MB adaptive weights
__device__ float g_wwt[Nn * O2];
__device__ float g_wws[Nn * O8];
__device__ float g_bias[Nn * On];
__device__ float g_X0[Nn * BCp];
__device__ float g_Y1[Nn * BCp];
__device__ float g_Y1s[Nn * BCp];
__device__ float g_Y2[Nn * BCp];
__device__ float g_pp[(size_t)SPL * Nn * BCp];  // 13.8 MB split-K partials
__device__ float g_XE[R48 * En];
__device__ float g_hpart[SPL * R48 * En];
__device__ float g_XEST[En * R48];
__device__ float g_ipart[SPL * Nn * R48];
__device__ float g_Mm[Bn * Nn];
__device__ float g_G[Nn];
__device__ float g_ts[Bn * Nn];

// ---------------- helpers ----------------
__device__ __forceinline__ void fma2(ull& acc, ull a, ull b) {
    asm("fma.rn.f32x2 %0, %1, %2, %0;" : "+l"(acc) : "l"(a), "l"(b));
}
__device__ __forceinline__ ull pack2(float lo, float hi) {
    ull r;
    asm("mov.b64 %0, {%1,%2};" : "=l"(r) : "f"(lo), "f"(hi));
    return r;
}
__device__ __forceinline__ void unpack2(float& lo, float& hi, ull v) {
    asm("mov.b64 {%0,%1}, %2;" : "=f"(lo), "=f"(hi) : "l"(v));
}

__device__ __forceinline__ float blk_reduce(float v, float* red, bool do_max) {
    int tid = threadIdx.x;
    red[tid] = v;
    __syncthreads();
#pragma unroll
    for (int s = 128; s > 0; s >>= 1) {
        if (tid < s) red[tid] = do_max ? fmaxf(red[tid], red[tid + s]) : (red[tid] + red[tid + s]);
        __syncthreads();
    }
    float r = red[0];
    __syncthreads();
    return r;
}

// ---------------- kernels ----------------

__global__ void k_transpose_ne(const float* __restrict__ ne) {
    int idx = blockIdx.x * 256 + threadIdx.x;
    if (idx < Nn * Dn) {
        int n = idx >> 4, d = idx & 15;
        g_neT[d * Nn + n] = ne[idx];
    }
}

// Generic fp32 GEMM with f32x2 packed FMAs, transposed A smem tile, split-K over blockIdx.z.
// EPI=1: relu then diag=stay_cost (used for S0).
template <int BM, int BN, int BK, int TM, int TN, int EPI>
__global__ void k_sgemm2(const float* __restrict__ A, const float* __restrict__ B,
                         float* __restrict__ C, int M, int N, int K,
                         const int* __restrict__ stay_ptr) {
    constexpr int TXc = BN / TN, TYc = BM / TM, NT = TXc * TYc;
    constexpr int TNh = TN / 2;
    __shared__ __align__(16) float As[BK][BM + 4];
    __shared__ __align__(16) float Bs[BK][BN + 4];
    int tid = threadIdx.x;
    int tx = tid % TXc, ty = tid / TXc;
    int m0 = blockIdx.y * BM, n0 = blockIdx.x * BN;
    int kChunk = (K + gridDim.z - 1) / gridDim.z;
    int k0 = blockIdx.z * kChunk;
    int k1 = min(K, k0 + kChunk);
    ull acc[TM][TNh];
#pragma unroll
    for (int i = 0; i < TM; i++)
#pragma unroll
        for (int j = 0; j < TNh; j++) acc[i][j] = 0ull;

    for (int kb = k0; kb < k1; kb += BK) {
        for (int i = tid; i < BM * BK; i += NT) {
            int mm = i / BK, kk = i % BK;
            int gm = m0 + mm, gk = kb + kk;
            As[kk][mm] = (gm < M && gk < k1) ? A[(size_t)gm * K + gk] : 0.f;
        }
        for (int i = tid; i < BK * BN; i += NT) {
            int kk = i / BN, nn = i % BN;
            int gk = kb + kk, gn = n0 + nn;
            Bs[kk][nn] = (gk < k1 && gn < N) ? B[(size_t)gk * N + gn] : 0.f;
        }
        __syncthreads();
#pragma unroll
        for (int kk = 0; kk < BK; kk++) {
            float ra[TM];
            if constexpr (TM % 4 == 0) {
#pragma unroll
                for (int i = 0; i < TM / 4; i++) {
                    float4 v = *reinterpret_cast<const float4*>(&As[kk][ty * TM + 4 * i]);
                    ra[4 * i] = v.x; ra[4 * i + 1] = v.y; ra[4 * i + 2] = v.z; ra[4 * i + 3] = v.w;
                }
            } else {
#pragma unroll
                for (int i = 0; i < TM; i++) ra[i] = As[kk][ty * TM + i];
            }
            ull rb[TNh];
            const ull* bp = reinterpret_cast<const ull*>(&Bs[kk][tx * TN]);
#pragma unroll
            for (int j = 0; j < TNh; j++) rb[j] = bp[j];
#pragma unroll
            for (int i = 0; i < TM; i++) {
                ull a2 = pack2(ra[i], ra[i]);
#pragma unroll
                for (int j = 0; j < TNh; j++) fma2(acc[i][j], a2, rb[j]);
            }
        }
        __syncthreads();
    }

    float* Cp = C + (size_t)blockIdx.z * M * N;
#pragma unroll
    for (int i = 0; i < TM; i++) {
        int gm = m0 + ty * TM + i;
        if (gm < M) {
#pragma unroll
            for (int j = 0; j < TNh; j++) {
                float lo, hi;
                unpack2(lo, hi, acc[i][j]);
                int gn = n0 + tx * TN + 2 * j;
                if (EPI == 1) {
                    lo = fmaxf(lo, 0.f);
                    hi = fmaxf(hi, 0.f);
                    float sc = (float)stay_ptr[0];
                    if (gm == gn) lo = sc;
                    if (gm == gn + 1) hi = sc;
                }
                if (gn < N) Cp[(size_t)gm * N + gn] = lo;
                if (gn + 1 < N) Cp[(size_t)gm * N + gn + 1] = hi;
            }
        }
    }
}

// per-row: softmax (fixed_adj==0) or adj*exp (else); writes row back + rowsum r
__global__ void k_row_transform(const float* __restrict__ adj, const int* __restrict__ fa_ptr) {
    __shared__ float red[256];
    int row = blockIdx.x, tid = threadIdx.x;
    float* srow = g_S + (size_t)row * Nn;
    float v[8];
#pragma unroll
    for (int i = 0; i < 8; i++) {
        int idx = i * 256 + tid;
        v[i] = (idx < Nn) ? srow[idx] : NEG_HUGE;
    }
    float rsum;
    if (fa_ptr[0] == 0) {
        float m = NEG_HUGE;
#pragma unroll
        for (int i = 0; i < 8; i++) m = fmaxf(m, v[i]);
        m = blk_reduce(m, red, true);
        float z = 0.f;
#pragma unroll
        for (int i = 0; i < 8; i++) {
            v[i] = expf(v[i] - m);
            z += v[i];
        }
        z = blk_reduce(z, red, false);
        float inv = 1.f / z;
        float s2 = 0.f;
#pragma unroll
        for (int i = 0; i < 8; i++) {
            v[i] *= inv;
            s2 += v[i];
        }
        rsum = blk_reduce(s2, red, false);
    } else {
        float s2 = 0.f;
#pragma unroll
        for (int i = 0; i < 8; i++) {
            int idx = i * 256 + tid;
            float sv = 0.f;
            if (idx < Nn) sv = adj[(size_t)row * Nn + idx] * expf(v[i]);
            v[i] = sv;
            s2 += sv;
        }
        rsum = blk_reduce(s2, red, false);
    }
#pragma unroll
    for (int i = 0; i < 8; i++) {
        int idx = i * 256 + tid;
        if (idx < Nn) srow[idx] = v[i];
    }
    if (tid == 0) g_r[row] = rsum;
}

__global__ void k_prep_x0(const float* __restrict__ x) {
    int idx = blockIdx.x * 256 + threadIdx.x;
    if (idx < Nn * BCp) {
        int n = idx / BCp, j = idx % BCp;
        float v = 0.f;
        if (j < BC) {
            int b = j / Cn, c = j % Cn;
            v = x[((size_t)b * Nn + n) * Cn + c] / g_r[n];
        }
        g_X0[idx] = v;
    }
}

// reduce SPL split-K planes of g_pp -> Y; optionally also write Y/r for next GEMM
template <int DO_SCALE>
__global__ void k_reduceY(float* __restrict__ Y, float* __restrict__ Ys) {
    int idx = blockIdx.x * 256 + threadIdx.x;
    if (idx < Nn * BCp) {
        float s = 0.f;
#pragma unroll
        for (int p = 0; p < SPL; p++) s += g_pp[(size_t)p * Nn * BCp + idx];
        Y[idx] = s;
        if (DO_SCALE) Ys[idx] = s / g_r[idx / BCp];
    }
}

__global__ void k_prep_xe(const float* __restrict__ xew, const int* __restrict__ bidx,
                          const float* __restrict__ lw, const float* __restrict__ lb) {
    int idx = blockIdx.x * 256 + threadIdx.x;
    if (idx < R48 * En) {
        int r = idx / En, e = idx % En;
        int b = r / NBn, f = r % NBn;
        int t = bidx[f];
        g_XE[idx] = xew[((size_t)(b * Wn_ + t)) * En + e] * lw[0] + lb[0];
    }
}

__global__ void k_tsum(const float* __restrict__ xw, const float* __restrict__ Tp) {
    int idx = blockIdx.x * 256 + threadIdx.x;
    if (idx < Bn * Nn) {
        int b = idx / Nn, n = idx % Nn;
        float s = 0.f;
#pragma unroll
        for (int t = 0; t < Wn_; t++) s += xw[((size_t)(b * Wn_ + t)) * Nn + n] * Tp[t];
        g_ts[idx] = s;
    }
}

__global__ void k_rowsum_g(const float* __restrict__ gw) {
    __shared__ float red[256];
    int row = blockIdx.x, tid = threadIdx.x;
    float s = 0.f;
    for (int i = tid; i < Nn; i += 256) s += gw[(size_t)row * Nn + i];
    s = blk_reduce(s, red, false);
    if (tid == 0) g_G[row] = s;
}

// reduce split-K hodge partials + jump-cost prefix, write transposed (E,48)
__global__ void k_hreduce(const int* __restrict__ jump_ptr) {
    int e = blockIdx.x * 256 + threadIdx.x;
    int r = blockIdx.y;
    if (e < En) {
        float v = 0.f;
#pragma unroll
        for (int p = 0; p < SPL; p++) v += g_hpart[(size_t)p * R48 * En + r * En + e];
        int b = r / NBn, f = r % NBn;
        float jc = (float)jump_ptr[0];
        for (int fp = 0; fp < f; fp++) v += jc * g_XE[(b * NBn + fp) * En + e];
        g_XEST[e * R48 + r] = v;
    }
}

// reduce split-K incidence partials + mean over bootstrap frames
__global__ void k_mreduce() {
    int idx = blockIdx.x * 256 + threadIdx.x;
    if (idx < Bn * Nn) {
        int b = idx / Nn, n = idx % Nn;
        float v = 0.f;
#pragma unroll
        for (int f = 0; f < NBn; f++) {
            int r = b * NBn + f;
#pragma unroll
            for (int p = 0; p < SPL; p++) v += g_ipart[(size_t)p * Nn * R48 + n * R48 + r];
        }
        g_Mm[idx] = v * (1.f / NBn);
    }
}

// fused per-node epilogue: diffusion conv + ZFC + temporal + supra + bias
__global__ void k_epilogue(const float* __restrict__ x, const float* __restrict__ zin,
                           const float* __restrict__ gnnb, float* __restrict__ out) {
    __shared__ float Wns[KC * O4];   // 3264
    __shared__ float xs[Bn * 52];
    __shared__ float bias_s[On];
    __shared__ float wwt_s[O2];
    __shared__ float wws_s[O8];
    __shared__ float ts_s[Bn];
    __shared__ float Ms_s[Bn];
    int n = blockIdx.x, tid = threadIdx.x;
    for (int i = tid; i < KC * O4; i += 256) Wns[i] = g_W[(size_t)n * KC * O4 + i];
    for (int i = tid; i < Bn * KC; i += 256) {
        int b = i / KC, kc = i % KC;
        int k = kc / Cn, c = kc % Cn;
        float v;
        if (k == 0) v = x[((size_t)b * Nn + n) * Cn + c];
        else if (k == 1) v = g_Y1[n * BCp + b * Cn + c];
        else v = g_Y2[n * BCp + b * Cn + c];
        xs[b * 52 + kc] = v;
    }
    bias_s[tid] = g_bias[n * On + tid];
    if (tid < O2) wwt_s[tid] = g_wwt[n * O2 + tid];
    if (tid < O8) wws_s[tid] = g_wws[n * O8 + tid];
    if (tid < Bn) {
        ts_s[tid] = g_ts[tid * Nn + n];
        Ms_s[tid] = g_Mm[tid * Nn + n];
    }
    __syncthreads();
    int b = tid >> 4;
    int oc = (tid & 15) * 4;
    ull acc2[2] = {0ull, 0ull};
    for (int kc = 0; kc < KC; kc++) {
        float a = xs[b * 52 + kc];
        ull a2 = pack2(a, a);
        const ull* wp2 = reinterpret_cast<const ull*>(&Wns[kc * O4 + oc]);
        fma2(acc2[0], a2, wp2[0]);
        fma2(acc2[1], a2, wp2[1]);
    }
    float acc[4];
    unpack2(acc[0], acc[1], acc2[0]);
    unpack2(acc[2], acc[3], acc2[1]);
    float* orow = out + ((size_t)b * Nn + n) * On;
#pragma unroll
    for (int j = 0; j < 4; j++) orow[oc + j] = acc[j] + bias_s[oc + j];
#pragma unroll
    for (int it = 0; it < 12; it++) {
        int o = 64 + (tid & 15) + it * 16;
        float v;
        if (o < 96) {
            int c = o - 64;
            int flat = n * O8 + c;
            int i2 = flat / Nn;
            int m = flat - i2 * Nn;
            v = fmaxf(zin[b * O8 + i2] * g_G[m] + gnnb[m], 0.f);
        } else if (o < 224) {
            v = ts_s[b] * wwt_s[o - 96];
        } else {
            v = Ms_s[b] * wws_s[o - 224];
        }
        orow[o] = v + bias_s[o];
    }
}

// ---------------- launch ----------------
extern "C" void kernel_launch(void* const* d_in, const int* in_sizes, int n_in,
                              void* d_out, int out_size) {
    const float* x    = (const float*)d_in[0];
    const float* xw   = (const float*)d_in[1];
    const float* ne   = (const float*)d_in[2];
    const int*   fa   = (const int*)d_in[3];
    const float* adj  = (const float*)d_in[4];
    const int*   stay = (const int*)d_in[5];
    const int*   jump = (const int*)d_in[6];
    const float* zin  = (const float*)d_in[7];
    const float* hodge= (const float*)d_in[8];
    const float* xew  = (const float*)d_in[9];
    const float* inc  = (const float*)d_in[10];
    const float* wp   = (const float*)d_in[11];
    const float* wwsp = (const float*)d_in[12];
    const float* wwtp = (const float*)d_in[13];
    const float* bp   = (const float*)d_in[14];
    const float* Tp   = (const float*)d_in[15];
    const float* lw   = (const float*)d_in[16];
    const float* lb   = (const float*)d_in[17];
    const float* gw   = (const float*)d_in[18];
    const float* gb   = (const float*)d_in[19];
    const int*   bidx = (const int*)d_in[20];
    float* out = (float*)d_out;

    float *pNeT, *pS, *pW, *pWwt, *pWws, *pBias, *pX0, *pY1, *pY1s, *pY2, *pPP, *pXE, *pH, *pXEST, *pI;
    cudaGetSymbolAddress((void**)&pNeT, g_neT);
    cudaGetSymbolAddress((void**)&pS, g_S);
    cudaGetSymbolAddress((void**)&pW, g_W);
    cudaGetSymbolAddress((void**)&pWwt, g_wwt);
    cudaGetSymbolAddress((void**)&pWws, g_wws);
    cudaGetSymbolAddress((void**)&pBias, g_bias);
    cudaGetSymbolAddress((void**)&pX0, g_X0);
    cudaGetSymbolAddress((void**)&pY1, g_Y1);
    cudaGetSymbolAddress((void**)&pY1s, g_Y1s);
    cudaGetSymbolAddress((void**)&pY2, g_Y2);
    cudaGetSymbolAddress((void**)&pPP, g_pp);
    cudaGetSymbolAddress((void**)&pXE, g_XE);
    cudaGetSymbolAddress((void**)&pH, g_hpart);
    cudaGetSymbolAddress((void**)&pXEST, g_XEST);
    cudaGetSymbolAddress((void**)&pI, g_ipart);

    // S branch: S0 = relu(ne@neT) w/ diag=stay, then row softmax + rowsums
    k_transpose_ne<<<(Nn * Dn + 255) / 256, 256>>>(ne);
    k_sgemm2<64, 64, 16, 4, 4, 1><<<dim3(32, 32, 1), 256>>>(ne, pNeT, pS, Nn, Nn, Dn, stay);
    k_row_transform<<<Nn, 256>>>(adj, fa);

    // adaptive params from node embeddings (K=16 GEMMs)
    k_sgemm2<64, 64, 16, 4, 4, 0><<<dim3(51, 32, 1), 256>>>(ne, wp, pW, Nn, KC * O4, Dn, nullptr);
    k_sgemm2<64, 64, 16, 4, 4, 0><<<dim3(2, 32, 1), 256>>>(ne, wwtp, pWwt, Nn, O2, Dn, nullptr);
    k_sgemm2<64, 64, 16, 4, 4, 0><<<dim3(1, 32, 1), 256>>>(ne, wwsp, pWws, Nn, O8, Dn, nullptr);
    k_sgemm2<64, 64, 16, 4, 4, 0><<<dim3(4, 32, 1), 256>>>(ne, bp, pBias, Nn, On, Dn, nullptr);

    // diffusion: Y1 = S @ (x/r), Y2 = S @ (Y1/r)   (split-K + fused-scale reduce)
    k_prep_x0<<<(Nn * BCp + 255) / 256, 256>>>(x);
    k_sgemm2<128, 96, 16, 8, 6, 0><<<dim3(3, 16, SPL), 256>>>(pS, pX0, pPP, Nn, BCp, Nn, nullptr);
    k_reduceY<1><<<(Nn * BCp + 255) / 256, 256>>>(pY1, pY1s);
    k_sgemm2<128, 96, 16, 8, 6, 0><<<dim3(3, 16, SPL), 256>>>(pS, pY1s, pPP, Nn, BCp, Nn, nullptr);
    k_reduceY<0><<<(Nn * BCp + 255) / 256, 256>>>(pY2, nullptr);

    // supra branch (structured supra-Laplacian, never materialized)
    k_prep_xe<<<(R48 * En + 255) / 256, 256>>>(xew, bidx, lw, lb);
    k_sgemm2<48, 64, 16, 3, 4, 0><<<dim3(47, 1, SPL), 256>>>(pXE, hodge, pH, R48, En, En, nullptr);
    k_hreduce<<<dim3((En + 255) / 256, R48), 256>>>(jump);
    k_sgemm2<64, 48, 16, 4, 6, 0><<<dim3(1, 32, SPL), 128>>>(inc, pXEST, pI, Nn, R48, En, nullptr);
    k_mreduce<<<(Bn * Nn + 255) / 256, 256>>>();

    // temporal + ZFC precompute
    k_tsum<<<(Bn * Nn + 255) / 256, 256>>>(xw, Tp);
    k_rowsum_g<<<Nn, 256>>>(gw);

    // fused epilogue: assemble all four regions + bias
    k_epilogue<<<Nn, 256>>>(x, zin, gb, out);
}

// round 4
// speedup vs baseline: 2.9684x; 1.8405x over previous
#include <cuda_runtime.h>

typedef unsigned long long ull;

// dims
constexpr int Bn = 16, Nn = 2000, En = 3000, Cn = 17, Wn_ = 12, Dn = 16, On = 256, Kk = 3, NBn = 3;
constexpr int BC = Bn * Cn;   // 272
constexpr int BCp = 288;      // padded column count for diffusion GEMMs
constexpr int KC = Kk * Cn;   // 51
constexpr int O4 = On / 4, O8 = On / 8, O2 = On / 2;
constexpr int SPL = 6;        // split-K planes (diffusion, hodge)
constexpr int SPLI = 10;      // split-K planes (incidence)

#define NEG_HUGE -1e30f

// ---------------- scratch (static device globals; no allocs) ----------------
__device__ float g_neT[Dn * Nn];
__device__ float g_S[(size_t)Nn * Nn];          // 16 MB
__device__ float g_r[Nn];                        // reciprocal row sums
__device__ float g_W[(size_t)Nn * KC * O4];     // 26 MB adaptive weights
__device__ float g_wwt[Nn * O2];
__device__ float g_wws[Nn * O8];
__device__ float g_bias[Nn * On];
__device__ float g_X0[Nn * BCp];
__device__ float g_Y1[Nn * BCp];
__device__ float g_Y2[Nn * BCp];
__device__ float g_pp[(size_t)SPL * Nn * BCp];  // split-K partials (diffusion)
__device__ float g_XEu[Bn * En];
__device__ float g_XEv[Bn * En];
__device__ float g_hpart[SPL * Bn * En];
__device__ float g_XEST[En * Bn];
__device__ float g_ipart[SPLI * Nn * Bn];
__device__ float g_Mm[Bn * Nn];
__device__ float g_G[Nn];
__device__ float g_ts[Bn * Nn];

// ---------------- helpers ----------------
__device__ __forceinline__ void fma2(ull& acc, ull a, ull b) {
    asm("fma.rn.f32x2 %0, %1, %2, %0;" : "+l"(acc) : "l"(a), "l"(b));
}
__device__ __forceinline__ ull pack2(float lo, float hi) {
    ull r;
    asm("mov.b64 %0, {%1,%2};" : "=l"(r) : "f"(lo), "f"(hi));
    return r;
}
__device__ __forceinline__ void unpack2(float& lo, float& hi, ull v) {
    asm("mov.b64 {%0,%1}, %2;" : "=f"(lo), "=f"(hi) : "l"(v));
}

__device__ __forceinline__ float blk_reduce(float v, float* red, bool do_max) {
    int tid = threadIdx.x;
    red[tid] = v;
    __syncthreads();
#pragma unroll
    for (int s = 128; s > 0; s >>= 1) {
        if (tid < s) red[tid] = do_max ? fmaxf(red[tid], red[tid + s]) : (red[tid] + red[tid + s]);
        __syncthreads();
    }
    float r = red[0];
    __syncthreads();
    return r;
}

// ---------------- kernels ----------------

__global__ void k_transpose_ne(const float* __restrict__ ne) {
    int idx = blockIdx.x * 256 + threadIdx.x;
    if (idx < Nn * Dn) {
        int n = idx >> 4, d = idx & 15;
        g_neT[d * Nn + n] = ne[idx];
    }
}

// K=16 GEMM (f32x2). EPI=1: relu + diag=stay (for S0). EPI=0: vectorized float4 store.
template <int BM, int BN, int BK, int TM, int TN, int EPI>
__global__ void k_sgemm2(const float* __restrict__ A, const float* __restrict__ B,
                         float* __restrict__ C, int M, int N, int K,
                         const int* __restrict__ stay_ptr) {
    constexpr int TXc = BN / TN, TYc = BM / TM, NT = TXc * TYc;
    constexpr int TNh = TN / 2;
    __shared__ __align__(16) float As[BK][BM + 4];
    __shared__ __align__(16) float Bs[BK][BN + 4];
    int tid = threadIdx.x;
    int tx = tid % TXc, ty = tid / TXc;
    int m0 = blockIdx.y * BM, n0 = blockIdx.x * BN;
    ull acc[TM][TNh];
#pragma unroll
    for (int i = 0; i < TM; i++)
#pragma unroll
        for (int j = 0; j < TNh; j++) acc[i][j] = 0ull;

    for (int kb = 0; kb < K; kb += BK) {
        for (int i = tid; i < BM * BK; i += NT) {
            int mm = i / BK, kk = i % BK;
            int gm = m0 + mm, gk = kb + kk;
            As[kk][mm] = (gm < M && gk < K) ? A[(size_t)gm * K + gk] : 0.f;
        }
        for (int i = tid; i < BK * BN; i += NT) {
            int kk = i / BN, nn = i % BN;
            int gk = kb + kk, gn = n0 + nn;
            Bs[kk][nn] = (gk < K && gn < N) ? B[(size_t)gk * N + gn] : 0.f;
        }
        __syncthreads();
#pragma unroll
        for (int kk = 0; kk < BK; kk++) {
            float ra[TM];
            if constexpr (TM % 4 == 0) {
#pragma unroll
                for (int i = 0; i < TM / 4; i++) {
                    float4 v = *reinterpret_cast<const float4*>(&As[kk][ty * TM + 4 * i]);
                    ra[4 * i] = v.x; ra[4 * i + 1] = v.y; ra[4 * i + 2] = v.z; ra[4 * i + 3] = v.w;
                }
            } else {
#pragma unroll
                for (int i = 0; i < TM; i++) ra[i] = As[kk][ty * TM + i];
            }
            ull rb[TNh];
            const ull* bp = reinterpret_cast<const ull*>(&Bs[kk][tx * TN]);
#pragma unroll
            for (int j = 0; j < TNh; j++) rb[j] = bp[j];
#pragma unroll
            for (int i = 0; i < TM; i++) {
                ull a2 = pack2(ra[i], ra[i]);
#pragma unroll
                for (int j = 0; j < TNh; j++) fma2(acc[i][j], a2, rb[j]);
            }
        }
        __syncthreads();
    }

#pragma unroll
    for (int i = 0; i < TM; i++) {
        int gm = m0 + ty * TM + i;
        if (gm < M) {
            int gnb = n0 + tx * TN;
            if (EPI == 0 && TN == 4 && gnb + 3 < N) {
                float4 v4;
                unpack2(v4.x, v4.y, acc[i][0]);
                unpack2(v4.z, v4.w, acc[i][1]);
                *reinterpret_cast<float4*>(&C[(size_t)gm * N + gnb]) = v4;
            } else {
#pragma unroll
                for (int j = 0; j < TNh; j++) {
                    float lo, hi;
                    unpack2(lo, hi, acc[i][j]);
                    int gn = gnb + 2 * j;
                    if (EPI == 1) {
                        lo = fmaxf(lo, 0.f);
                        hi = fmaxf(hi, 0.f);
                        float sc = (float)stay_ptr[0];
                        if (gm == gn) lo = sc;
                        if (gm == gn + 1) hi = sc;
                    }
                    if (gn < N) C[(size_t)gm * N + gn] = lo;
                    if (gn + 1 < N) C[(size_t)gm * N + gn + 1] = hi;
                }
            }
        }
    }
}

// Double-buffered split-K SGEMM. SCALE_A: multiply A columns by rinv[gk].
// Requires K % 4 == 0. Writes partial plane z of C (M*N each).
template <int BM, int BN, int BK, int TM, int TN, int NT, int SCALE_A>
__global__ void __launch_bounds__(NT) k_dbgemm(
        const float* __restrict__ A, const float* __restrict__ B,
        float* __restrict__ C, int M, int N, int K, int kChunk,
        const float* __restrict__ rinv) {
    constexpr int TXc = BN / TN, TYc = BM / TM;
    static_assert(TXc * TYc == NT, "thread count");
    constexpr int TNh = TN / 2;
    constexpr int AV = BM * BK / 4;  // float4 count per A tile
    constexpr int BV = BK * BN / 4;
    constexpr int AU = (AV + NT - 1) / NT;
    constexpr int BU = (BV + NT - 1) / NT;
    __shared__ __align__(16) float As[2][BK][BM + 4];
    __shared__ __align__(16) float Bs[2][BK][BN + 4];
    int tid = threadIdx.x;
    int tx = tid % TXc, ty = tid / TXc;
    int m0 = blockIdx.y * BM, n0 = blockIdx.x * BN;
    int k0 = blockIdx.z * kChunk;
    int k1 = min(K, k0 + kChunk);

    float4 ar[AU], br[BU];

    auto loadA = [&](int kb) {
#pragma unroll
        for (int u = 0; u < AU; u++) {
            int v = u * NT + tid;
            float4 val = {0.f, 0.f, 0.f, 0.f};
            if (AV % NT == 0 || v < AV) {
                int mm = v / (BK / 4);
                int kk = (v % (BK / 4)) * 4;
                int gm = m0 + mm, gk = kb + kk;
                if (gm < M && gk < K) {
                    val = *reinterpret_cast<const float4*>(A + (size_t)gm * K + gk);
                    if (SCALE_A) {
                        val.x *= rinv[gk];
                        val.y *= rinv[gk + 1];
                        val.z *= rinv[gk + 2];
                        val.w *= rinv[gk + 3];
                    }
                }
            }
            ar[u] = val;
        }
    };
    auto storeA = [&](int st) {
#pragma unroll
        for (int u = 0; u < AU; u++) {
            int v = u * NT + tid;
            if (AV % NT == 0 || v < AV) {
                int mm = v / (BK / 4);
                int kk = (v % (BK / 4)) * 4;
                As[st][kk + 0][mm] = ar[u].x;
                As[st][kk + 1][mm] = ar[u].y;
                As[st][kk + 2][mm] = ar[u].z;
                As[st][kk + 3][mm] = ar[u].w;
            }
        }
    };
    auto loadB = [&](int kb) {
#pragma unroll
        for (int u = 0; u < BU; u++) {
            int v = u * NT + tid;
            float4 val = {0.f, 0.f, 0.f, 0.f};
            if (BV % NT == 0 || v < BV) {
                int kk = v / (BN / 4);
                int nn = (v % (BN / 4)) * 4;
                int gk = kb + kk, gn = n0 + nn;
                if (gk < k1 && gn < N)
                    val = *reinterpret_cast<const float4*>(B + (size_t)gk * N + gn);
            }
            br[u] = val;
        }
    };
    auto storeB = [&](int st) {
#pragma unroll
        for (int u = 0; u < BU; u++) {
            int v = u * NT + tid;
            if (BV % NT == 0 || v < BV) {
                int kk = v / (BN / 4);
                int nn = (v % (BN / 4)) * 4;
                *reinterpret_cast<float4*>(&Bs[st][kk][nn]) = br[u];
            }
        }
    };

    ull acc[TM][TNh];
#pragma unroll
    for (int i = 0; i < TM; i++)
#pragma unroll
        for (int j = 0; j < TNh; j++) acc[i][j] = 0ull;

    int ntiles = (k1 > k0) ? (k1 - k0 + BK - 1) / BK : 0;
    if (ntiles > 0) {
        loadA(k0);
        loadB(k0);
        storeA(0);
        storeB(0);
    }
    int cur = 0;
    for (int t = 0; t < ntiles; t++) {
        __syncthreads();
        bool have_next = (t + 1 < ntiles);
        if (have_next) {
            int kbn = k0 + (t + 1) * BK;
            loadA(kbn);
            loadB(kbn);
        }
#pragma unroll
        for (int kk = 0; kk < BK; kk++) {
            float ra[TM];
            if constexpr (TM % 4 == 0) {
#pragma unroll
                for (int i = 0; i < TM / 4; i++) {
                    float4 v = *reinterpret_cast<const float4*>(&As[cur][kk][ty * TM + 4 * i]);
                    ra[4 * i] = v.x; ra[4 * i + 1] = v.y; ra[4 * i + 2] = v.z; ra[4 * i + 3] = v.w;
                }
            } else {
#pragma unroll
                for (int i = 0; i < TM; i++) ra[i] = As[cur][kk][ty * TM + i];
            }
            ull rb[TNh];
            const ull* bp = reinterpret_cast<const ull*>(&Bs[cur][kk][tx * TN]);
#pragma unroll
            for (int j = 0; j < TNh; j++) rb[j] = bp[j];
#pragma unroll
            for (int i = 0; i < TM; i++) {
                ull a2 = pack2(ra[i], ra[i]);
#pragma unroll
                for (int j = 0; j < TNh; j++) fma2(acc[i][j], a2, rb[j]);
            }
        }
        if (have_next) {
            storeA(1 - cur);
            storeB(1 - cur);
            cur ^= 1;
        }
    }

    float* Cp = C + (size_t)blockIdx.z * M * N;
#pragma unroll
    for (int i = 0; i < TM; i++) {
        int gm = m0 + ty * TM + i;
        if (gm < M) {
#pragma unroll
            for (int j = 0; j < TNh; j++) {
                float lo, hi;
                unpack2(lo, hi, acc[i][j]);
                int gn = n0 + tx * TN + 2 * j;
                if (gn < N) Cp[(size_t)gm * N + gn] = lo;
                if (gn + 1 < N) Cp[(size_t)gm * N + gn + 1] = hi;
            }
        }
    }
}

// per-row: softmax (fixed_adj==0) or adj*exp; writes row back + reciprocal rowsum
__global__ void k_row_transform(const float* __restrict__ adj, const int* __restrict__ fa_ptr) {
    __shared__ float red[256];
    int row = blockIdx.x, tid = threadIdx.x;
    float* srow = g_S + (size_t)row * Nn;
    float v[8];
#pragma unroll
    for (int i = 0; i < 8; i++) {
        int idx = i * 256 + tid;
        v[i] = (idx < Nn) ? srow[idx] : NEG_HUGE;
    }
    float rsum;
    if (fa_ptr[0] == 0) {
        float m = NEG_HUGE;
#pragma unroll
        for (int i = 0; i < 8; i++) m = fmaxf(m, v[i]);
        m = blk_reduce(m, red, true);
        float z = 0.f;
#pragma unroll
        for (int i = 0; i < 8; i++) {
            v[i] = expf(v[i] - m);
            z += v[i];
        }
        z = blk_reduce(z, red, false);
        float inv = 1.f / z;
        float s2 = 0.f;
#pragma unroll
        for (int i = 0; i < 8; i++) {
            v[i] *= inv;
            s2 += v[i];
        }
        rsum = blk_reduce(s2, red, false);
    } else {
        float s2 = 0.f;
#pragma unroll
        for (int i = 0; i < 8; i++) {
            int idx = i * 256 + tid;
            float sv = 0.f;
            if (idx < Nn) sv = adj[(size_t)row * Nn + idx] * expf(v[i]);
            v[i] = sv;
            s2 += sv;
        }
        rsum = blk_reduce(s2, red, false);
    }
#pragma unroll
    for (int i = 0; i < 8; i++) {
        int idx = i * 256 + tid;
        if (idx < Nn) srow[idx] = v[i];
    }
    if (tid == 0) g_r[row] = 1.f / rsum;
}

__global__ void k_prep_x0(const float* __restrict__ x) {
    int idx = blockIdx.x * 256 + threadIdx.x;
    if (idx < Nn * BCp) {
        int n = idx / BCp, j = idx % BCp;
        float v = 0.f;
        if (j < BC) {
            int b = j / Cn, c = j % Cn;
            v = x[((size_t)b * Nn + n) * Cn + c];
        }
        g_X0[idx] = v;
    }
}

__global__ void k_reduceY(float* __restrict__ Y) {
    int idx = blockIdx.x * 256 + threadIdx.x;
    if (idx < Nn * BCp) {
        float s = 0.f;
#pragma unroll
        for (int p = 0; p < SPL; p++) s += g_pp[(size_t)p * Nn * BCp + idx];
        Y[idx] = s;
    }
}

// mean / weighted-prefix combos of bootstrap-gathered edge signals
__global__ void k_prep_xe2(const float* __restrict__ xew, const int* __restrict__ bidx,
                           const float* __restrict__ lw, const float* __restrict__ lb) {
    int idx = blockIdx.x * 256 + threadIdx.x;
    if (idx < Bn * En) {
        int b = idx / En, e = idx % En;
        float xs[NBn];
#pragma unroll
        for (int f = 0; f < NBn; f++) {
            int t = bidx[f];
            xs[f] = xew[((size_t)(b * Wn_ + t)) * En + e] * lw[0] + lb[0];
        }
        g_XEu[idx] = (xs[0] + xs[1] + xs[2]) * (1.f / 3.f);
        g_XEv[idx] = (2.f * xs[0] + xs[1]) * (1.f / 3.f);
    }
}

__global__ void k_tsum(const float* __restrict__ xw, const float* __restrict__ Tp) {
    int idx = blockIdx.x * 256 + threadIdx.x;
    if (idx < Bn * Nn) {
        int b = idx / Nn, n = idx % Nn;
        float s = 0.f;
#pragma unroll
        for (int t = 0; t < Wn_; t++) s += xw[((size_t)(b * Wn_ + t)) * Nn + n] * Tp[t];
        g_ts[idx] = s;
    }
}

__global__ void k_rowsum_g(const float* __restrict__ gw) {
    __shared__ float red[256];
    int row = blockIdx.x, tid = threadIdx.x;
    float s = 0.f;
    for (int i = tid; i < Nn; i += 256) s += gw[(size_t)row * Nn + i];
    s = blk_reduce(s, red, false);
    if (tid == 0) g_G[row] = s;
}

// reduce hodge split-K partials + jump*v, write transposed (E,16)
__global__ void k_hreduce(const int* __restrict__ jump_ptr) {
    int e = blockIdx.x * 256 + threadIdx.x;
    int b = blockIdx.y;
    if (e < En) {
        float v = 0.f;
#pragma unroll
        for (int p = 0; p < SPL; p++) v += g_hpart[(size_t)p * Bn * En + b * En + e];
        v += (float)jump_ptr[0] * g_XEv[b * En + e];
        g_XEST[e * Bn + b] = v;
    }
}

__global__ void k_mreduce() {
    int idx = blockIdx.x * 256 + threadIdx.x;
    if (idx < Bn * Nn) {
        int b = idx / Nn, n = idx % Nn;
        float v = 0.f;
#pragma unroll
        for (int p = 0; p < SPLI; p++) v += g_ipart[(size_t)p * Nn * Bn + n * Bn + b];
        g_Mm[idx] = v;
    }
}

// fused per-node epilogue: diffusion conv + ZFC + temporal + supra + bias
__global__ void k_epilogue(const float* __restrict__ x, const float* __restrict__ zin,
                           const float* __restrict__ gnnb, float* __restrict__ out) {
    __shared__ float Wns[KC * O4];
    __shared__ float xs[Bn * 52];
    __shared__ float bias_s[On];
    __shared__ float wwt_s[O2];
    __shared__ float wws_s[O8];
    __shared__ float ts_s[Bn];
    __shared__ float Ms_s[Bn];
    int n = blockIdx.x, tid = threadIdx.x;
    for (int i = tid; i < KC * O4; i += 256) Wns[i] = g_W[(size_t)n * KC * O4 + i];
    for (int i = tid; i < Bn * KC; i += 256) {
        int b = i / KC, kc = i % KC;
        int k = kc / Cn, c = kc % Cn;
        float v;
        if (k == 0) v = x[((size_t)b * Nn + n) * Cn + c];
        else if (k == 1) v = g_Y1[n * BCp + b * Cn + c];
        else v = g_Y2[n * BCp + b * Cn + c];
        xs[b * 52 + kc] = v;
    }
    bias_s[tid] = g_bias[n * On + tid];
    if (tid < O2) wwt_s[tid] = g_wwt[n * O2 + tid];
    if (tid < O8) wws_s[tid] = g_wws[n * O8 + tid];
    if (tid < Bn) {
        ts_s[tid] = g_ts[tid * Nn + n];
        Ms_s[tid] = g_Mm[tid * Nn + n];
    }
    __syncthreads();
    int b = tid >> 4;
    int oc = (tid & 15) * 4;
    ull acc2[2] = {0ull, 0ull};
    for (int kc = 0; kc < KC; kc++) {
        float a = xs[b * 52 + kc];
        ull a2 = pack2(a, a);
        const ull* wp2 = reinterpret_cast<const ull*>(&Wns[kc * O4 + oc]);
        fma2(acc2[0], a2, wp2[0]);
        fma2(acc2[1], a2, wp2[1]);
    }
    float acc[4];
    unpack2(acc[0], acc[1], acc2[0]);
    unpack2(acc[2], acc[3], acc2[1]);
    float* orow = out + ((size_t)b * Nn + n) * On;
#pragma unroll
    for (int j = 0; j < 4; j++) orow[oc + j] = acc[j] + bias_s[oc + j];
#pragma unroll
    for (int it = 0; it < 12; it++) {
        int o = 64 + (tid & 15) + it * 16;
        float v;
        if (o < 96) {
            int c = o - 64;
            int flat = n * O8 + c;
            int i2 = flat / Nn;
            int m = flat - i2 * Nn;
            v = fmaxf(zin[b * O8 + i2] * g_G[m] + gnnb[m], 0.f);
        } else if (o < 224) {
            v = ts_s[b] * wwt_s[o - 96];
        } else {
            v = Ms_s[b] * wws_s[o - 224];
        }
        orow[o] = v + bias_s[o];
    }
}

// ---------------- launch ----------------
extern "C" void kernel_launch(void* const* d_in, const int* in_sizes, int n_in,
                              void* d_out, int out_size) {
    const float* x    = (const float*)d_in[0];
    const float* xw   = (const float*)d_in[1];
    const float* ne   = (const float*)d_in[2];
    const int*   fa   = (const int*)d_in[3];
    const float* adj  = (const float*)d_in[4];
    const int*   stay = (const int*)d_in[5];
    const int*   jump = (const int*)d_in[6];
    const float* zin  = (const float*)d_in[7];
    const float* hodge= (const float*)d_in[8];
    const float* xew  = (const float*)d_in[9];
    const float* inc  = (const float*)d_in[10];
    const float* wp   = (const float*)d_in[11];
    const float* wwsp = (const float*)d_in[12];
    const float* wwtp = (const float*)d_in[13];
    const float* bp   = (const float*)d_in[14];
    const float* Tp   = (const float*)d_in[15];
    const float* lw   = (const float*)d_in[16];
    const float* lb   = (const float*)d_in[17];
    const float* gw   = (const float*)d_in[18];
    const float* gb   = (const float*)d_in[19];
    const int*   bidx = (const int*)d_in[20];
    float* out = (float*)d_out;

    float *pNeT, *pS, *pR, *pW, *pWwt, *pWws, *pBias, *pX0, *pY1, *pY2, *pPP;
    float *pXEu, *pH, *pXEST, *pI;
    cudaGetSymbolAddress((void**)&pNeT, g_neT);
    cudaGetSymbolAddress((void**)&pS, g_S);
    cudaGetSymbolAddress((void**)&pR, g_r);
    cudaGetSymbolAddress((void**)&pW, g_W);
    cudaGetSymbolAddress((void**)&pWwt, g_wwt);
    cudaGetSymbolAddress((void**)&pWws, g_wws);
    cudaGetSymbolAddress((void**)&pBias, g_bias);
    cudaGetSymbolAddress((void**)&pX0, g_X0);
    cudaGetSymbolAddress((void**)&pY1, g_Y1);
    cudaGetSymbolAddress((void**)&pY2, g_Y2);
    cudaGetSymbolAddress((void**)&pPP, g_pp);
    cudaGetSymbolAddress((void**)&pXEu, g_XEu);
    cudaGetSymbolAddress((void**)&pH, g_hpart);
    cudaGetSymbolAddress((void**)&pXEST, g_XEST);
    cudaGetSymbolAddress((void**)&pI, g_ipart);

    // S branch: S0 = relu(ne@neT) w/ diag=stay, then row softmax + reciprocal rowsums
    k_transpose_ne<<<(Nn * Dn + 255) / 256, 256>>>(ne);
    k_sgemm2<64, 64, 16, 4, 4, 1><<<dim3(32, 32), 256>>>(ne, pNeT, pS, Nn, Nn, Dn, stay);
    k_row_transform<<<Nn, 256>>>(adj, fa);

    // adaptive params from node embeddings (K=16 GEMMs)
    k_sgemm2<64, 64, 16, 4, 4, 0><<<dim3(51, 32), 256>>>(ne, wp, pW, Nn, KC * O4, Dn, nullptr);
    k_sgemm2<64, 64, 16, 4, 4, 0><<<dim3(2, 32), 256>>>(ne, wwtp, pWwt, Nn, O2, Dn, nullptr);
    k_sgemm2<64, 64, 16, 4, 4, 0><<<dim3(1, 32), 256>>>(ne, wwsp, pWws, Nn, O8, Dn, nullptr);
    k_sgemm2<64, 64, 16, 4, 4, 0><<<dim3(4, 32), 256>>>(ne, bp, pBias, Nn, On, Dn, nullptr);

    // diffusion: Y1 = (S/r)@x, Y2 = (S/r)@Y1  (scaling fused into A-tile load)
    k_prep_x0<<<(Nn * BCp + 255) / 256, 256>>>(x);
    constexpr int bigChunk = 336;  // ceil(2000/6) -> mult of 16
    k_dbgemm<128, 96, 16, 8, 6, 256, 1><<<dim3(3, 16, SPL), 256>>>(pS, pX0, pPP, Nn, BCp, Nn, bigChunk, pR);
    k_reduceY<<<(Nn * BCp + 255) / 256, 256>>>(pY1);
    k_dbgemm<128, 96, 16, 8, 6, 256, 1><<<dim3(3, 16, SPL), 256>>>(pS, pY1, pPP, Nn, BCp, Nn, bigChunk, pR);
    k_reduceY<<<(Nn * BCp + 255) / 256, 256>>>(pY2);

    // supra branch (mean-over-frames folded: u@hodge + jump*v, then @ inc^T)
    k_prep_xe2<<<(Bn * En + 255) / 256, 256>>>(xew, bidx, lw, lb);
    constexpr int hChunk = 512;  // ceil(3000/6) -> mult of 16
    k_dbgemm<16, 128, 16, 2, 8, 128, 0><<<dim3(24, 1, SPL), 128>>>(pXEu, hodge, pH, Bn, En, En, hChunk, nullptr);
    k_hreduce<<<dim3((En + 255) / 256, Bn), 256>>>(jump);
    constexpr int iChunk = 304;  // ceil(3000/10) -> mult of 16
    k_dbgemm<128, 16, 16, 8, 2, 128, 0><<<dim3(1, 16, SPLI), 128>>>(inc, pXEST, pI, Nn, Bn, En, iChunk, nullptr);
    k_mreduce<<<(Bn * Nn + 255) / 256, 256>>>();

    // temporal + ZFC precompute
    k_tsum<<<(Bn * Nn + 255) / 256, 256>>>(xw, Tp);
    k_rowsum_g<<<Nn, 256>>>(gw);

    // fused epilogue
    k_epilogue<<<Nn, 256>>>(x, zin, gb, out);
}

// round 7
// speedup vs baseline: 4.1730x; 1.4058x over previous
#include <cuda_runtime.h>
#include <cstdint>

typedef unsigned long long ull;

// dims
constexpr int Bn = 16, Nn = 2000, En = 3000, Cn = 17, Wn_ = 12, Dn = 16, On = 256, Kk = 3, NBn = 3;
constexpr int BC = Bn * Cn;   // 272
constexpr int BCp = 288;      // padded column count for diffusion GEMMs
constexpr int KC = Kk * Cn;   // 51
constexpr int O4 = On / 4, O8 = On / 8, O2 = On / 2;
constexpr int SPL = 6;        // split-K planes (diffusion, hodge)
constexpr int SPLI = 10;      // split-K planes (incidence)

#define NEG_HUGE -1e30f

// ---------------- scratch (static device globals; no allocs) ----------------
__device__ float g_neT[Dn * Nn];
__device__ float g_S[(size_t)Nn * Nn];          // 16 MB
__device__ float g_r[Nn];                        // reciprocal row sums
__device__ float g_W[(size_t)Nn * KC * O4];     // 26 MB adaptive weights
__device__ float g_wwt[Nn * O2];
__device__ float g_wws[Nn * O8];
__device__ float g_bias[Nn * On];
__device__ float g_X0[Nn * BCp];
__device__ float g_Y1[Nn * BCp];
__device__ float g_Y2[Nn * BCp];
__device__ float g_pp[(size_t)SPL * Nn * BCp];  // split-K partials (diffusion)
__device__ float g_XEu[Bn * En];
__device__ float g_XEv[Bn * En];
__device__ float g_hpart[SPL * Bn * En];
__device__ float g_XEST[En * Bn];
__device__ float g_ipart[SPLI * Nn * Bn];
__device__ float g_Mm[Bn * Nn];
__device__ float g_G[Nn];
__device__ float g_ts[Bn * Nn];

// ---------------- helpers ----------------
__device__ __forceinline__ void fma2(ull& acc, ull a, ull b) {
    asm("fma.rn.f32x2 %0, %1, %2, %0;" : "+l"(acc) : "l"(a), "l"(b));
}
__device__ __forceinline__ ull pack2(float lo, float hi) {
    ull r;
    asm("mov.b64 %0, {%1,%2};" : "=l"(r) : "f"(lo), "f"(hi));
    return r;
}
__device__ __forceinline__ void unpack2(float& lo, float& hi, ull v) {
    asm("mov.b64 {%0,%1}, %2;" : "=f"(lo), "=f"(hi) : "l"(v));
}
__device__ __forceinline__ float f2tf(float f) {
    uint32_t r;
    asm("cvt.rna.tf32.f32 %0, %1;" : "=r"(r) : "f"(f));
    return __uint_as_float(r);
}
__device__ __forceinline__ void mma_tf32(float* d, const uint32_t* a, const uint32_t* b) {
    asm("mma.sync.aligned.m16n8k8.row.col.f32.tf32.tf32.f32 "
        "{%0,%1,%2,%3}, {%4,%5,%6,%7}, {%8,%9}, {%0,%1,%2,%3};"
        : "+f"(d[0]), "+f"(d[1]), "+f"(d[2]), "+f"(d[3])
        : "r"(a[0]), "r"(a[1]), "r"(a[2]), "r"(a[3]), "r"(b[0]), "r"(b[1]));
}

__device__ __forceinline__ float blk_reduce(float v, float* red, bool do_max) {
    int tid = threadIdx.x;
    red[tid] = v;
    __syncthreads();
#pragma unroll
    for (int s = 128; s > 0; s >>= 1) {
        if (tid < s) red[tid] = do_max ? fmaxf(red[tid], red[tid + s]) : (red[tid] + red[tid + s]);
        __syncthreads();
    }
    float r = red[0];
    __syncthreads();
    return r;
}

// ---------------- kernels ----------------

__global__ void k_transpose_ne(const float* __restrict__ ne) {
    int idx = blockIdx.x * 256 + threadIdx.x;
    if (idx < Nn * Dn) {
        int n = idx >> 4, d = idx & 15;
        g_neT[d * Nn + n] = ne[idx];
    }
}

// K=16 GEMM (f32x2). EPI=1: relu + diag=stay (for S0). EPI=0: vectorized float4 store.
template <int BM, int BN, int BK, int TM, int TN, int EPI>
__global__ void k_sgemm2(const float* __restrict__ A, const float* __restrict__ B,
                         float* __restrict__ C, int M, int N, int K,
                         const int* __restrict__ stay_ptr) {
    constexpr int TXc = BN / TN, TYc = BM / TM, NT = TXc * TYc;
    constexpr int TNh = TN / 2;
    __shared__ __align__(16) float As[BK][BM + 4];
    __shared__ __align__(16) float Bs[BK][BN + 4];
    int tid = threadIdx.x;
    int tx = tid % TXc, ty = tid / TXc;
    int m0 = blockIdx.y * BM, n0 = blockIdx.x * BN;
    ull acc[TM][TNh];
#pragma unroll
    for (int i = 0; i < TM; i++)
#pragma unroll
        for (int j = 0; j < TNh; j++) acc[i][j] = 0ull;

    for (int kb = 0; kb < K; kb += BK) {
        for (int i = tid; i < BM * BK; i += NT) {
            int mm = i / BK, kk = i % BK;
            int gm = m0 + mm, gk = kb + kk;
            As[kk][mm] = (gm < M && gk < K) ? A[(size_t)gm * K + gk] : 0.f;
        }
        for (int i = tid; i < BK * BN; i += NT) {
            int kk = i / BN, nn = i % BN;
            int gk = kb + kk, gn = n0 + nn;
            Bs[kk][nn] = (gk < K && gn < N) ? B[(size_t)gk * N + gn] : 0.f;
        }
        __syncthreads();
#pragma unroll
        for (int kk = 0; kk < BK; kk++) {
            float ra[TM];
            if constexpr (TM % 4 == 0) {
#pragma unroll
                for (int i = 0; i < TM / 4; i++) {
                    float4 v = *reinterpret_cast<const float4*>(&As[kk][ty * TM + 4 * i]);
                    ra[4 * i] = v.x; ra[4 * i + 1] = v.y; ra[4 * i + 2] = v.z; ra[4 * i + 3] = v.w;
                }
            } else {
#pragma unroll
                for (int i = 0; i < TM; i++) ra[i] = As[kk][ty * TM + i];
            }
            ull rb[TNh];
            const ull* bp = reinterpret_cast<const ull*>(&Bs[kk][tx * TN]);
#pragma unroll
            for (int j = 0; j < TNh; j++) rb[j] = bp[j];
#pragma unroll
            for (int i = 0; i < TM; i++) {
                ull a2 = pack2(ra[i], ra[i]);
#pragma unroll
                for (int j = 0; j < TNh; j++) fma2(acc[i][j], a2, rb[j]);
            }
        }
        __syncthreads();
    }

#pragma unroll
    for (int i = 0; i < TM; i++) {
        int gm = m0 + ty * TM + i;
        if (gm < M) {
            int gnb = n0 + tx * TN;
            if (EPI == 0 && TN == 4 && gnb + 3 < N) {
                float4 v4;
                unpack2(v4.x, v4.y, acc[i][0]);
                unpack2(v4.z, v4.w, acc[i][1]);
                *reinterpret_cast<float4*>(&C[(size_t)gm * N + gnb]) = v4;
            } else {
#pragma unroll
                for (int j = 0; j < TNh; j++) {
                    float lo, hi;
                    unpack2(lo, hi, acc[i][j]);
                    int gn = gnb + 2 * j;
                    if (EPI == 1) {
                        lo = fmaxf(lo, 0.f);
                        hi = fmaxf(hi, 0.f);
                        float sc = (float)stay_ptr[0];
                        if (gm == gn) lo = sc;
                        if (gm == gn + 1) hi = sc;
                    }
                    if (gn < N) C[(size_t)gm * N + gn] = lo;
                    if (gn + 1 < N) C[(size_t)gm * N + gn + 1] = hi;
                }
            }
        }
    }
}

// ---------------- tf32 tensor-core GEMM (m16n8k8), double-buffered, split-K ----
// A row-major MxK fp32, B row-major KxN fp32. Writes partial plane z (M*N).
// SCALE_A: multiply A column gk by rinv[gk] before conversion.
// Warp layout: NWARP = NT/32 warps arranged (NWARP/WCOL) x WCOL.
// Warp tile: (MI*16) x (NI*8). Requires kChunk % 4 == 0.
template <int BM, int BN, int BK, int WCOL, int MI, int NI, int NT, int SCALE_A>
__global__ void __launch_bounds__(NT) k_tfgemm(
        const float* __restrict__ A, const float* __restrict__ B,
        float* __restrict__ C, int M, int N, int K, int kChunk,
        const float* __restrict__ rinv) {
    constexpr int NWARP = NT / 32;
    constexpr int WROW = NWARP / WCOL;
    static_assert(WROW * MI * 16 == BM, "BM");
    static_assert(WCOL * NI * 8 == BN, "BN");
    constexpr int PAD = 4;
    __shared__ __align__(16) float As[2][BK][BM + PAD];
    __shared__ __align__(16) float Bs[2][BK][BN + PAD];
    int tid = threadIdx.x;
    int wid = tid >> 5, lane = tid & 31;
    int wm = wid / WCOL, wn = wid % WCOL;
    int g = lane >> 2, tg = lane & 3;
    int m0 = blockIdx.y * BM, n0 = blockIdx.x * BN;
    int k0 = blockIdx.z * kChunk;
    int k1 = min(K, k0 + kChunk);

    constexpr int AV = BM * BK / 4;
    constexpr int BV = BK * BN / 4;
    constexpr int AU = (AV + NT - 1) / NT;
    constexpr int BU = (BV + NT - 1) / NT;
    float4 ar[AU], br[BU];

    auto loadA = [&](int kb) {
#pragma unroll
        for (int u = 0; u < AU; u++) {
            int v = u * NT + tid;
            float4 val = {0.f, 0.f, 0.f, 0.f};
            if (AV % NT == 0 || v < AV) {
                int mm = v / (BK / 4);
                int kk = (v % (BK / 4)) * 4;
                int gm = m0 + mm, gk = kb + kk;
                if (gm < M && gk < k1) {
                    val = *reinterpret_cast<const float4*>(A + (size_t)gm * K + gk);
                    if (SCALE_A) {
                        val.x *= rinv[gk];
                        val.y *= rinv[gk + 1];
                        val.z *= rinv[gk + 2];
                        val.w *= rinv[gk + 3];
                    }
                }
            }
            ar[u] = val;
        }
    };
    auto storeA = [&](int st) {
#pragma unroll
        for (int u = 0; u < AU; u++) {
            int v = u * NT + tid;
            if (AV % NT == 0 || v < AV) {
                int mm = v / (BK / 4);
                int kk = (v % (BK / 4)) * 4;
                As[st][kk + 0][mm] = f2tf(ar[u].x);
                As[st][kk + 1][mm] = f2tf(ar[u].y);
                As[st][kk + 2][mm] = f2tf(ar[u].z);
                As[st][kk + 3][mm] = f2tf(ar[u].w);
            }
        }
    };
    auto loadB = [&](int kb) {
#pragma unroll
        for (int u = 0; u < BU; u++) {
            int v = u * NT + tid;
            float4 val = {0.f, 0.f, 0.f, 0.f};
            if (BV % NT == 0 || v < BV) {
                int kk = v / (BN / 4);
                int nn = (v % (BN / 4)) * 4;
                int gk = kb + kk, gn = n0 + nn;
                if (gk < k1 && gn < N)
                    val = *reinterpret_cast<const float4*>(B + (size_t)gk * N + gn);
            }
            br[u] = val;
        }
    };
    auto storeB = [&](int st) {
#pragma unroll
        for (int u = 0; u < BU; u++) {
            int v = u * NT + tid;
            if (BV % NT == 0 || v < BV) {
                int kk = v / (BN / 4);
                int nn = (v % (BN / 4)) * 4;
                float4 val = br[u];
                val.x = f2tf(val.x);
                val.y = f2tf(val.y);
                val.z = f2tf(val.z);
                val.w = f2tf(val.w);
                *reinterpret_cast<float4*>(&Bs[st][kk][nn]) = val;
            }
        }
    };

    float acc[MI][NI][4];
#pragma unroll
    for (int i = 0; i < MI; i++)
#pragma unroll
        for (int j = 0; j < NI; j++)
#pragma unroll
            for (int q = 0; q < 4; q++) acc[i][j][q] = 0.f;

    int ntiles = (k1 > k0) ? (k1 - k0 + BK - 1) / BK : 0;
    if (ntiles > 0) {
        loadA(k0);
        loadB(k0);
        storeA(0);
        storeB(0);
    }
    int cur = 0;
    for (int t = 0; t < ntiles; t++) {
        __syncthreads();
        bool have_next = (t + 1 < ntiles);
        if (have_next) {
            int kbn = k0 + (t + 1) * BK;
            loadA(kbn);
            loadB(kbn);
        }
#pragma unroll
        for (int k8 = 0; k8 < BK; k8 += 8) {
            uint32_t afr[MI][4];
            uint32_t bfr[NI][2];
#pragma unroll
            for (int mi = 0; mi < MI; mi++) {
                int mb = wm * MI * 16 + mi * 16;
                afr[mi][0] = __float_as_uint(As[cur][k8 + tg][mb + g]);
                afr[mi][1] = __float_as_uint(As[cur][k8 + tg][mb + g + 8]);
                afr[mi][2] = __float_as_uint(As[cur][k8 + tg + 4][mb + g]);
                afr[mi][3] = __float_as_uint(As[cur][k8 + tg + 4][mb + g + 8]);
            }
#pragma unroll
            for (int ni = 0; ni < NI; ni++) {
                int nb = wn * NI * 8 + ni * 8;
                bfr[ni][0] = __float_as_uint(Bs[cur][k8 + tg][nb + g]);
                bfr[ni][1] = __float_as_uint(Bs[cur][k8 + tg + 4][nb + g]);
            }
#pragma unroll
            for (int mi = 0; mi < MI; mi++)
#pragma unroll
                for (int ni = 0; ni < NI; ni++) mma_tf32(acc[mi][ni], afr[mi], bfr[ni]);
        }
        if (have_next) {
            storeA(1 - cur);
            storeB(1 - cur);
            cur ^= 1;
        }
    }

    float* Cp = C + (size_t)blockIdx.z * M * N;
#pragma unroll
    for (int mi = 0; mi < MI; mi++) {
#pragma unroll
        for (int ni = 0; ni < NI; ni++) {
            int r0 = m0 + wm * MI * 16 + mi * 16 + g;
            int c0 = n0 + wn * NI * 8 + ni * 8 + 2 * tg;
#pragma unroll
            for (int half = 0; half < 2; half++) {
                int rr = r0 + half * 8;
                if (rr < M) {
                    float v0 = acc[mi][ni][2 * half];
                    float v1 = acc[mi][ni][2 * half + 1];
                    if (c0 + 1 < N) {
                        float2 v2 = {v0, v1};
                        *reinterpret_cast<float2*>(&Cp[(size_t)rr * N + c0]) = v2;
                    } else if (c0 < N) {
                        Cp[(size_t)rr * N + c0] = v0;
                    }
                }
            }
        }
    }
}

// per-row: softmax (fixed_adj==0) or adj*exp; writes row back + reciprocal rowsum
__global__ void k_row_transform(const float* __restrict__ adj, const int* __restrict__ fa_ptr) {
    __shared__ float red[256];
    int row = blockIdx.x, tid = threadIdx.x;
    float* srow = g_S + (size_t)row * Nn;
    float v[8];
#pragma unroll
    for (int i = 0; i < 8; i++) {
        int idx = i * 256 + tid;
        v[i] = (idx < Nn) ? srow[idx] : NEG_HUGE;
    }
    float rsum;
    if (fa_ptr[0] == 0) {
        float m = NEG_HUGE;
#pragma unroll
        for (int i = 0; i < 8; i++) m = fmaxf(m, v[i]);
        m = blk_reduce(m, red, true);
        float z = 0.f;
#pragma unroll
        for (int i = 0; i < 8; i++) {
            v[i] = expf(v[i] - m);
            z += v[i];
        }
        z = blk_reduce(z, red, false);
        float inv = 1.f / z;
        float s2 = 0.f;
#pragma unroll
        for (int i = 0; i < 8; i++) {
            v[i] *= inv;
            s2 += v[i];
        }
        rsum = blk_reduce(s2, red, false);
    } else {
        float s2 = 0.f;
#pragma unroll
        for (int i = 0; i < 8; i++) {
            int idx = i * 256 + tid;
            float sv = 0.f;
            if (idx < Nn) sv = adj[(size_t)row * Nn + idx] * expf(v[i]);
            v[i] = sv;
            s2 += sv;
        }
        rsum = blk_reduce(s2, red, false);
    }
#pragma unroll
    for (int i = 0; i < 8; i++) {
        int idx = i * 256 + tid;
        if (idx < Nn) srow[idx] = v[i];
    }
    if (tid == 0) g_r[row] = 1.f / rsum;
}

__global__ void k_prep_x0(const float* __restrict__ x) {
    int idx = blockIdx.x * 256 + threadIdx.x;
    if (idx < Nn * BCp) {
        int n = idx / BCp, j = idx % BCp;
        float v = 0.f;
        if (j < BC) {
            int b = j / Cn, c = j % Cn;
            v = x[((size_t)b * Nn + n) * Cn + c];
        }
        g_X0[idx] = v;
    }
}

__global__ void k_reduceY(float* __restrict__ Y) {
    int idx = blockIdx.x * 256 + threadIdx.x;
    if (idx < Nn * BCp) {
        float s = 0.f;
#pragma unroll
        for (int p = 0; p < SPL; p++) s += g_pp[(size_t)p * Nn * BCp + idx];
        Y[idx] = s;
    }
}

// mean / weighted-prefix combos of bootstrap-gathered edge signals
__global__ void k_prep_xe2(const float* __restrict__ xew, const int* __restrict__ bidx,
                           const float* __restrict__ lw, const float* __restrict__ lb) {
    int idx = blockIdx.x * 256 + threadIdx.x;
    if (idx < Bn * En) {
        int b = idx / En, e = idx % En;
        float xs[NBn];
#pragma unroll
        for (int f = 0; f < NBn; f++) {
            int t = bidx[f];
            xs[f] = xew[((size_t)(b * Wn_ + t)) * En + e] * lw[0] + lb[0];
        }
        g_XEu[idx] = (xs[0] + xs[1] + xs[2]) * (1.f / 3.f);
        g_XEv[idx] = (2.f * xs[0] + xs[1]) * (1.f / 3.f);
    }
}

__global__ void k_tsum(const float* __restrict__ xw, const float* __restrict__ Tp) {
    int idx = blockIdx.x * 256 + threadIdx.x;
    if (idx < Bn * Nn) {
        int b = idx / Nn, n = idx % Nn;
        float s = 0.f;
#pragma unroll
        for (int t = 0; t < Wn_; t++) s += xw[((size_t)(b * Wn_ + t)) * Nn + n] * Tp[t];
        g_ts[idx] = s;
    }
}

__global__ void k_rowsum_g(const float* __restrict__ gw) {
    __shared__ float red[256];
    int row = blockIdx.x, tid = threadIdx.x;
    float s = 0.f;
    for (int i = tid; i < Nn; i += 256) s += gw[(size_t)row * Nn + i];
    s = blk_reduce(s, red, false);
    if (tid == 0) g_G[row] = s;
}

// reduce hodge split-K partials + jump*v, write transposed (E,16)
__global__ void k_hreduce(const int* __restrict__ jump_ptr) {
    int e = blockIdx.x * 256 + threadIdx.x;
    int b = blockIdx.y;
    if (e < En) {
        float v = 0.f;
#pragma unroll
        for (int p = 0; p < SPL; p++) v += g_hpart[(size_t)p * Bn * En + b * En + e];
        v += (float)jump_ptr[0] * g_XEv[b * En + e];
        g_XEST[e * Bn + b] = v;
    }
}

__global__ void k_mreduce() {
    int idx = blockIdx.x * 256 + threadIdx.x;
    if (idx < Bn * Nn) {
        int b = idx / Nn, n = idx % Nn;
        float v = 0.f;
#pragma unroll
        for (int p = 0; p < SPLI; p++) v += g_ipart[(size_t)p * Nn * Bn + n * Bn + b];
        g_Mm[idx] = v;
    }
}

// fused per-node epilogue: diffusion conv + ZFC + temporal + supra + bias
__global__ void k_epilogue(const float* __restrict__ x, const float* __restrict__ zin,
                           const float* __restrict__ gnnb, float* __restrict__ out) {
    __shared__ float Wns[KC * O4];
    __shared__ float xs[Bn * 52];
    __shared__ float bias_s[On];
    __shared__ float wwt_s[O2];
    __shared__ float wws_s[O8];
    __shared__ float ts_s[Bn];
    __shared__ float Ms_s[Bn];
    int n = blockIdx.x, tid = threadIdx.x;
    for (int i = tid; i < KC * O4; i += 256) Wns[i] = g_W[(size_t)n * KC * O4 + i];
    for (int i = tid; i < Bn * KC; i += 256) {
        int b = i / KC, kc = i % KC;
        int k = kc / Cn, c = kc % Cn;
        float v;
        if (k == 0) v = x[((size_t)b * Nn + n) * Cn + c];
        else if (k == 1) v = g_Y1[n * BCp + b * Cn + c];
        else v = g_Y2[n * BCp + b * Cn + c];
        xs[b * 52 + kc] = v;
    }
    bias_s[tid] = g_bias[n * On + tid];
    if (tid < O2) wwt_s[tid] = g_wwt[n * O2 + tid];
    if (tid < O8) wws_s[tid] = g_wws[n * O8 + tid];
    if (tid < Bn) {
        ts_s[tid] = g_ts[tid * Nn + n];
        Ms_s[tid] = g_Mm[tid * Nn + n];
    }
    __syncthreads();
    int b = tid >> 4;
    int oc = (tid & 15) * 4;
    ull acc2[2] = {0ull, 0ull};
    for (int kc = 0; kc < KC; kc++) {
        float a = xs[b * 52 + kc];
        ull a2 = pack2(a, a);
        const ull* wp2 = reinterpret_cast<const ull*>(&Wns[kc * O4 + oc]);
        fma2(acc2[0], a2, wp2[0]);
        fma2(acc2[1], a2, wp2[1]);
    }
    float acc[4];
    unpack2(acc[0], acc[1], acc2[0]);
    unpack2(acc[2], acc[3], acc2[1]);
    float* orow = out + ((size_t)b * Nn + n) * On;
#pragma unroll
    for (int j = 0; j < 4; j++) orow[oc + j] = acc[j] + bias_s[oc + j];
#pragma unroll
    for (int it = 0; it < 12; it++) {
        int o = 64 + (tid & 15) + it * 16;
        float v;
        if (o < 96) {
            int c = o - 64;
            int flat = n * O8 + c;
            int i2 = flat / Nn;
            int m = flat - i2 * Nn;
            v = fmaxf(zin[b * O8 + i2] * g_G[m] + gnnb[m], 0.f);
        } else if (o < 224) {
            v = ts_s[b] * wwt_s[o - 96];
        } else {
            v = Ms_s[b] * wws_s[o - 224];
        }
        orow[o] = v + bias_s[o];
    }
}

// ---------------- launch ----------------
extern "C" void kernel_launch(void* const* d_in, const int* in_sizes, int n_in,
                              void* d_out, int out_size) {
    const float* x    = (const float*)d_in[0];
    const float* xw   = (const float*)d_in[1];
    const float* ne   = (const float*)d_in[2];
    const int*   fa   = (const int*)d_in[3];
    const float* adj  = (const float*)d_in[4];
    const int*   stay = (const int*)d_in[5];
    const int*   jump = (const int*)d_in[6];
    const float* zin  = (const float*)d_in[7];
    const float* hodge= (const float*)d_in[8];
    const float* xew  = (const float*)d_in[9];
    const float* inc  = (const float*)d_in[10];
    const float* wp   = (const float*)d_in[11];
    const float* wwsp = (const float*)d_in[12];
    const float* wwtp = (const float*)d_in[13];
    const float* bp   = (const float*)d_in[14];
    const float* Tp   = (const float*)d_in[15];
    const float* lw   = (const float*)d_in[16];
    const float* lb   = (const float*)d_in[17];
    const float* gw   = (const float*)d_in[18];
    const float* gb   = (const float*)d_in[19];
    const int*   bidx = (const int*)d_in[20];
    float* out = (float*)d_out;

    float *pNeT, *pS, *pR, *pW, *pWwt, *pWws, *pBias, *pX0, *pY1, *pY2, *pPP;
    float *pXEu, *pH, *pXEST, *pI;
    cudaGetSymbolAddress((void**)&pNeT, g_neT);
    cudaGetSymbolAddress((void**)&pS, g_S);
    cudaGetSymbolAddress((void**)&pR, g_r);
    cudaGetSymbolAddress((void**)&pW, g_W);
    cudaGetSymbolAddress((void**)&pWwt, g_wwt);
    cudaGetSymbolAddress((void**)&pWws, g_wws);
    cudaGetSymbolAddress((void**)&pBias, g_bias);
    cudaGetSymbolAddress((void**)&pX0, g_X0);
    cudaGetSymbolAddress((void**)&pY1, g_Y1);
    cudaGetSymbolAddress((void**)&pY2, g_Y2);
    cudaGetSymbolAddress((void**)&pPP, g_pp);
    cudaGetSymbolAddress((void**)&pXEu, g_XEu);
    cudaGetSymbolAddress((void**)&pH, g_hpart);
    cudaGetSymbolAddress((void**)&pXEST, g_XEST);
    cudaGetSymbolAddress((void**)&pI, g_ipart);

    // S branch: S0 = relu(ne@neT) w/ diag=stay, then row softmax + reciprocal rowsums
    k_transpose_ne<<<(Nn * Dn + 255) / 256, 256>>>(ne);
    k_sgemm2<64, 64, 16, 4, 4, 1><<<dim3(32, 32), 256>>>(ne, pNeT, pS, Nn, Nn, Dn, stay);
    k_row_transform<<<Nn, 256>>>(adj, fa);

    // adaptive params from node embeddings (K=16 GEMMs)
    k_sgemm2<64, 64, 16, 4, 4, 0><<<dim3(51, 32), 256>>>(ne, wp, pW, Nn, KC * O4, Dn, nullptr);
    k_sgemm2<64, 64, 16, 4, 4, 0><<<dim3(2, 32), 256>>>(ne, wwtp, pWwt, Nn, O2, Dn, nullptr);
    k_sgemm2<64, 64, 16, 4, 4, 0><<<dim3(1, 32), 256>>>(ne, wwsp, pWws, Nn, O8, Dn, nullptr);
    k_sgemm2<64, 64, 16, 4, 4, 0><<<dim3(4, 32), 256>>>(ne, bp, pBias, Nn, On, Dn, nullptr);

    // diffusion: Y1 = (S/r)@x, Y2 = (S/r)@Y1  (tf32 tensor cores, col-scale fused)
    k_prep_x0<<<(Nn * BCp + 255) / 256, 256>>>(x);
    constexpr int bigChunk = 336;  // mult of BK=16, covers 2000 over 6 planes
    k_tfgemm<128, 96, 16, 4, 4, 3, 256, 1><<<dim3(3, 16, SPL), 256>>>(pS, pX0, pPP, Nn, BCp, Nn, bigChunk, pR);
    k_reduceY<<<(Nn * BCp + 255) / 256, 256>>>(pY1);
    k_tfgemm<128, 96, 16, 4, 4, 3, 256, 1><<<dim3(3, 16, SPL), 256>>>(pS, pY1, pPP, Nn, BCp, Nn, bigChunk, pR);
    k_reduceY<<<(Nn * BCp + 255) / 256, 256>>>(pY2);

    // supra branch (mean-over-frames folded: u@hodge + jump*v, then @ inc^T)
    k_prep_xe2<<<(Bn * En + 255) / 256, 256>>>(xew, bidx, lw, lb);
    constexpr int hChunk = 512;  // mult of BK=32
    k_tfgemm<16, 128, 32, 4, 1, 4, 128, 0><<<dim3(24, 1, SPL), 128>>>(pXEu, hodge, pH, Bn, En, En, hChunk, nullptr);
    k_hreduce<<<dim3((En + 255) / 256, Bn), 256>>>(jump);
    constexpr int iChunk = 320;  // mult of BK=32 (tail guarded by k1)
    k_tfgemm<128, 16, 32, 1, 2, 2, 128, 0><<<dim3(1, 16, SPLI), 128>>>(inc, pXEST, pI, Nn, Bn, En, iChunk, nullptr);
    k_mreduce<<<(Bn * Nn + 255) / 256, 256>>>();

    // temporal + ZFC precompute
    k_tsum<<<(Bn * Nn + 255) / 256, 256>>>(xw, Tp);
    k_rowsum_g<<<Nn, 256>>>(gw);

    // fused epilogue
    k_epilogue<<<Nn, 256>>>(x, zin, gb, out);
}